// round 10
// baseline (speedup 1.0000x reference)
#include <cuda_runtime.h>

#define NN 50000
#define NE 600000
#define HID 128
#define TILE_N 64
#define KCH 32
#define SCAN_B 1024
#define NBLK ((NN + SCAN_B - 1) / SCAN_B)   // 49 scan blocks
#define EPW 8                                // edges per warp in alpha_kernel

typedef unsigned long long u64;

// Scratch (static device globals — no runtime allocation).
__device__ __align__(256) float g_q[(size_t)NN * HID];
__device__ __align__(256) float g_k[(size_t)NN * HID];
__device__ __align__(256) float g_v[(size_t)NN * HID];
__device__ __align__(256) float g_alpha[(size_t)NE * 8];  // per-edge per-head alpha
__device__ __align__(256) float g_WT[3 * HID * HID];
__device__ __align__(256) int   g_src[NE];
__device__ __align__(256) int   g_dst[NE];
__device__ __align__(256) int   g_count[NN];
__device__ __align__(256) int   g_start[NN + 1];
__device__ __align__(256) int   g_cursor[NN];
__device__ __align__(256) int2  g_es[NE];        // (edge id, src) sorted by dst
__device__ __align__(256) int   g_bsum[NBLK];
__device__ __align__(256) int   g_boff[NBLK];
__device__ int g_is_i32;

// ---------------------------------------------------------------------------
// f32x2 packed-FMA helpers (FFMA2 — PTX-only, exact fp32).
// ---------------------------------------------------------------------------
__device__ __forceinline__ u64 pack2(float lo, float hi) {
    u64 r; asm("mov.b64 %0, {%1, %2};" : "=l"(r) : "f"(lo), "f"(hi)); return r;
}
__device__ __forceinline__ void fma2(u64& acc, u64 a, u64 b) {
    asm("fma.rn.f32x2 %0, %1, %2, %0;" : "+l"(acc) : "l"(a), "l"(b));
}

// ---------------------------------------------------------------------------
// Kernel Z: zero counters + dtype flag + detection in one pass.
// ---------------------------------------------------------------------------
__global__ void zero_and_detect(const unsigned int* __restrict__ ei_words) {
    int t = blockIdx.x * blockDim.x + threadIdx.x;
    if (t == 0) g_is_i32 = 0;
    for (int i = t; i < NN; i += blockDim.x * gridDim.x) g_count[i] = 0;
    unsigned int acc = 0;
    for (int i = t; i < NE; i += blockDim.x * gridDim.x)
        acc |= ei_words[2 * i + 1];
    if (acc) atomicOr(&g_is_i32, 1);
}

// ---------------------------------------------------------------------------
// Kernel B: decode edge_index into g_src/g_dst AND histogram dst degrees.
// ---------------------------------------------------------------------------
__global__ void convert_idx(const unsigned int* __restrict__ ei_words) {
    int t = blockIdx.x * blockDim.x + threadIdx.x;
    int i32 = g_is_i32;
    for (int e = t; e < NE; e += blockDim.x * gridDim.x) {
        int s, d;
        if (i32) {
            s = (int)ei_words[e];
            d = (int)ei_words[NE + e];
        } else {
            s = (int)ei_words[2 * (size_t)e];
            d = (int)ei_words[2 * ((size_t)NE + e)];
        }
        g_src[e] = s;
        g_dst[e] = d;
        atomicAdd(&g_count[d], 1);
    }
}

// ---------------------------------------------------------------------------
// 3-phase parallel scan.
// ---------------------------------------------------------------------------
__global__ __launch_bounds__(SCAN_B) void scan_phase1() {
    __shared__ int ps[SCAN_B];
    int tid = threadIdx.x;
    int idx = blockIdx.x * SCAN_B + tid;
    int val = (idx < NN) ? g_count[idx] : 0;
    ps[tid] = val;
    __syncthreads();
#pragma unroll
    for (int d = 1; d < SCAN_B; d <<= 1) {
        int v = (tid >= d) ? ps[tid - d] : 0;
        __syncthreads();
        ps[tid] += v;
        __syncthreads();
    }
    if (idx < NN) g_start[idx] = ps[tid] - val;
    if (tid == SCAN_B - 1) g_bsum[blockIdx.x] = ps[tid];
}

__global__ void scan_phase2() {
    int l = threadIdx.x;             // 64 threads, NBLK=49 <= 64
    int v = (l < NBLK) ? g_bsum[l] : 0;
    int orig = v;
    __shared__ int s[64];
    s[l] = v;
    __syncthreads();
#pragma unroll
    for (int d = 1; d < 64; d <<= 1) {
        int t = (l >= d) ? s[l - d] : 0;
        __syncthreads();
        s[l] += t;
        __syncthreads();
    }
    if (l < NBLK) g_boff[l] = s[l] - orig;
    if (l == 63) g_start[NN] = s[63];
}

__global__ __launch_bounds__(SCAN_B) void scan_phase3() {
    int idx = blockIdx.x * SCAN_B + threadIdx.x;
    if (idx < NN) {
        int v = g_start[idx] + g_boff[blockIdx.x];
        g_start[idx] = v;
        g_cursor[idx] = v;
    }
}

// ---------------------------------------------------------------------------
// Kernel D: permute (edge id, src) pairs into dst-sorted order.
// ---------------------------------------------------------------------------
__global__ void permute_idx() {
    int t = blockIdx.x * blockDim.x + threadIdx.x;
    for (int e = t; e < NE; e += blockDim.x * gridDim.x) {
        int d = g_dst[e];
        int pos = atomicAdd(&g_cursor[d], 1);
        g_es[pos] = make_int2(e, g_src[e]);
    }
}

// ---------------------------------------------------------------------------
// Kernel 0: transpose the three 128x128 weight matrices (tiny).
// ---------------------------------------------------------------------------
__global__ void transpose_w(const float* __restrict__ Wq,
                            const float* __restrict__ Wk,
                            const float* __restrict__ Wv) {
    int t = blockIdx.x * blockDim.x + threadIdx.x;
    int total = 3 * HID * HID;
    for (int idx = t; idx < total; idx += blockDim.x * gridDim.x) {
        int m = idx / (HID * HID);
        int r = idx - m * (HID * HID);
        int o = r >> 7;
        int d = r & 127;
        const float* W = (m == 0) ? Wq : (m == 1) ? Wk : Wv;
        g_WT[m * HID * HID + d * HID + o] = W[o * HID + d];
    }
}

// ---------------------------------------------------------------------------
// Kernel 1: QKV GEMM (FFMA2), 3 CTAs/SM.
// ---------------------------------------------------------------------------
__global__ __launch_bounds__(256, 3) void qkv_gemm(const float* __restrict__ x,
                                                   int m_base) {
    __shared__ float wt[KCH][HID];
    __shared__ float xs[TILE_N][KCH];

    int m = blockIdx.y + m_base;
    const float* wtg = &g_WT[m * HID * HID];
    float* out = (m == 0) ? g_q : (m == 1) ? g_k : g_v;

    int node0 = blockIdx.x * TILE_N;
    int tid = threadIdx.x;
    int w = tid >> 5;
    int l = tid & 31;

    const float4* xg4 = (const float4*)x;
    int xn0 = tid >> 3,         xc0 = tid & 7;
    int xn1 = (tid + 256) >> 3, xc1 = (tid + 256) & 7;
    int gn0 = node0 + xn0, gn1 = node0 + xn1;

    u64 cxy[8], czw[8];
#pragma unroll
    for (int n = 0; n < 8; n++) { cxy[n] = 0ull; czw[n] = 0ull; }

#pragma unroll
    for (int kk = 0; kk < HID / KCH; kk++) {
        int k0 = kk * KCH;
        if (kk) __syncthreads();
        {
            float4* wt4 = (float4*)&wt[0][0];
            const float4* srcw = (const float4*)&wtg[(size_t)k0 * HID];
#pragma unroll
            for (int i = 0; i < 4; i++)
                wt4[tid + i * 256] = srcw[tid + i * 256];
        }
        {
            float4* xs4 = (float4*)&xs[0][0];
            xs4[tid] = (gn0 < NN) ? xg4[(size_t)gn0 * 32 + (k0 >> 2) + xc0]
                                  : make_float4(0.f, 0.f, 0.f, 0.f);
            xs4[tid + 256] = (gn1 < NN) ? xg4[(size_t)gn1 * 32 + (k0 >> 2) + xc1]
                                        : make_float4(0.f, 0.f, 0.f, 0.f);
        }
        __syncthreads();

#pragma unroll
        for (int d4 = 0; d4 < KCH / 4; d4++) {
            int d = d4 * 4;
            ulonglong2 w0 = *(ulonglong2*)&wt[d + 0][4 * l];
            ulonglong2 w1 = *(ulonglong2*)&wt[d + 1][4 * l];
            ulonglong2 w2 = *(ulonglong2*)&wt[d + 2][4 * l];
            ulonglong2 w3 = *(ulonglong2*)&wt[d + 3][4 * l];
#pragma unroll
            for (int n = 0; n < 8; n++) {
                float4 xv = *(float4*)&xs[8 * w + n][d];
                u64 xb0 = pack2(xv.x, xv.x);
                u64 xb1 = pack2(xv.y, xv.y);
                u64 xb2 = pack2(xv.z, xv.z);
                u64 xb3 = pack2(xv.w, xv.w);
                fma2(cxy[n], xb0, w0.x); fma2(czw[n], xb0, w0.y);
                fma2(cxy[n], xb1, w1.x); fma2(czw[n], xb1, w1.y);
                fma2(cxy[n], xb2, w2.x); fma2(czw[n], xb2, w2.y);
                fma2(cxy[n], xb3, w3.x); fma2(czw[n], xb3, w3.y);
            }
        }
    }

#pragma unroll
    for (int n = 0; n < 8; n++) {
        int gn = node0 + 8 * w + n;
        if (gn < NN) {
            ulonglong2 o2;
            o2.x = cxy[n];
            o2.y = czw[n];
            *(ulonglong2*)&out[(size_t)gn * HID + 4 * l] = o2;
        }
    }
}

// ---------------------------------------------------------------------------
// Kernel 2a: alpha in EDGE order, 8 edges per warp -> 24 LDG.128 in flight
// (random q/k gathers are latency-bound; MLP is the only lever). w_ij and
// cutoff streamed with __ldcs. Quad (4 lanes) = 1 head. Writes alpha[e][h]
// with cutoff and 1/sqrt(16) folded in.
// ---------------------------------------------------------------------------
__global__ __launch_bounds__(256) void alpha_kernel(
    const float* __restrict__ w_ij,
    const float* __restrict__ cutoff) {

    int wg = (blockIdx.x * blockDim.x + threadIdx.x) >> 5;
    int l = threadIdx.x & 31;
    int e0 = wg * EPW;
    if (e0 >= NE) return;   // NE % EPW == 0 -> no tail handling

    // Issue all loads first (compiler batches -> deep MLP), then reduce.
    float4 q[EPW], k[EPW], wv[EPW];
#pragma unroll
    for (int j = 0; j < EPW; j++) {
        int e = e0 + j;
        int s = g_src[e], d = g_dst[e];
        q[j]  = *(const float4*)&g_q[(size_t)d * HID + 4 * l];
        k[j]  = *(const float4*)&g_k[(size_t)s * HID + 4 * l];
        wv[j] = __ldcs((const float4*)&w_ij[(size_t)e * HID + 4 * l]);
    }

    float pr[EPW];
#pragma unroll
    for (int j = 0; j < EPW; j++) {
        pr[j] = q[j].x * wv[j].x * k[j].x + q[j].y * wv[j].y * k[j].y +
                q[j].z * wv[j].z * k[j].z + q[j].w * wv[j].w * k[j].w;
        pr[j] += __shfl_xor_sync(0xffffffffu, pr[j], 1);
        pr[j] += __shfl_xor_sync(0xffffffffu, pr[j], 2);
    }
    if ((l & 3) == 0) {
        int h = l >> 2;
#pragma unroll
        for (int j = 0; j < EPW; j++) {
            float c = __ldcs(&cutoff[e0 + j]);
            g_alpha[(size_t)(e0 + j) * 8 + h] = pr[j] * 0.25f * c;
        }
    }
}

// ---------------------------------------------------------------------------
// Kernel 2b: dst-sorted aggregation. One warp per node; per edge a v-gather
// (L2-resident) + 32B alpha gather. Unroll 4. No atomics.
// ---------------------------------------------------------------------------
__global__ __launch_bounds__(256) void edge_agg(float* __restrict__ out) {
    int node = (blockIdx.x * blockDim.x + threadIdx.x) >> 5;
    int l = threadIdx.x & 31;
    if (node >= NN) return;

    int p     = g_start[node];
    int e_end = g_start[node + 1];
    int h = l >> 2;

    float4 acc = make_float4(0.f, 0.f, 0.f, 0.f);

    for (; p + 4 <= e_end; p += 4) {
        int2 es0 = g_es[p];
        int2 es1 = g_es[p + 1];
        int2 es2 = g_es[p + 2];
        int2 es3 = g_es[p + 3];

        float4 v0 = *(const float4*)&g_v[(size_t)es0.y * HID + 4 * l];
        float4 v1 = *(const float4*)&g_v[(size_t)es1.y * HID + 4 * l];
        float4 v2 = *(const float4*)&g_v[(size_t)es2.y * HID + 4 * l];
        float4 v3 = *(const float4*)&g_v[(size_t)es3.y * HID + 4 * l];
        float a0 = g_alpha[(size_t)es0.x * 8 + h];
        float a1 = g_alpha[(size_t)es1.x * 8 + h];
        float a2 = g_alpha[(size_t)es2.x * 8 + h];
        float a3 = g_alpha[(size_t)es3.x * 8 + h];

        acc.x = fmaf(a0, v0.x, fmaf(a1, v1.x, fmaf(a2, v2.x, fmaf(a3, v3.x, acc.x))));
        acc.y = fmaf(a0, v0.y, fmaf(a1, v1.y, fmaf(a2, v2.y, fmaf(a3, v3.y, acc.y))));
        acc.z = fmaf(a0, v0.z, fmaf(a1, v1.z, fmaf(a2, v2.z, fmaf(a3, v3.z, acc.z))));
        acc.w = fmaf(a0, v0.w, fmaf(a1, v1.w, fmaf(a3, v3.w, fmaf(a2, v2.w, acc.w))));
    }
    for (; p < e_end; p++) {
        int2 es0 = g_es[p];
        float4 v0 = *(const float4*)&g_v[(size_t)es0.y * HID + 4 * l];
        float a0 = g_alpha[(size_t)es0.x * 8 + h];
        acc.x = fmaf(a0, v0.x, acc.x);
        acc.y = fmaf(a0, v0.y, acc.y);
        acc.z = fmaf(a0, v0.z, acc.z);
        acc.w = fmaf(a0, v0.w, acc.w);
    }

    __stcs((float4*)&out[(size_t)node * HID + 4 * l], acc);
}

// ---------------------------------------------------------------------------
extern "C" void kernel_launch(void* const* d_in, const int* in_sizes, int n_in,
                              void* d_out, int out_size) {
    const float* x      = (const float*)d_in[0];
    const float* w_ij   = (const float*)d_in[1];
    const unsigned int* ei = (const unsigned int*)d_in[2];
    const float* cutoff = (const float*)d_in[3];
    const float* Wq     = (const float*)d_in[4];
    const float* Wk     = (const float*)d_in[5];
    const float* Wv     = (const float*)d_in[6];
    float* out = (float*)d_out;

    static cudaStream_t s2 = nullptr;
    static cudaEvent_t evFork = nullptr, evQK = nullptr, evV = nullptr;
    static bool use_streams = false;
    if (!s2 && !evFork) {
        bool ok = (cudaStreamCreateWithFlags(&s2, cudaStreamNonBlocking) == cudaSuccess)
               && (cudaEventCreateWithFlags(&evFork, cudaEventDisableTiming) == cudaSuccess)
               && (cudaEventCreateWithFlags(&evQK, cudaEventDisableTiming) == cudaSuccess)
               && (cudaEventCreateWithFlags(&evV, cudaEventDisableTiming) == cudaSuccess);
        use_streams = ok;
    }

    int gx = (NN + TILE_N - 1) / TILE_N;
    int alpha_blocks = ((NE / EPW) * 32 + 255) / 256;  // warp per EPW edges
    int agg_blocks   = (NN * 32 + 255) / 256;          // warp per node

    if (use_streams) {
        // API issue order is arranged so alpha_kernel is the 6th launch
        // (ncu -s 5 -c 1 captures it); stream dependencies are unchanged.
        cudaEventRecord(evFork, 0);
        cudaStreamWaitEvent(s2, evFork, 0);

        transpose_w<<<48, 256>>>(Wq, Wk, Wv);                 // #0 main
        dim3 gqk(gx, 2);
        qkv_gemm<<<gqk, 256>>>(x, 0);                         // #1 main
        cudaEventRecord(evQK, 0);

        zero_and_detect<<<148, 256, 0, s2>>>(ei);             // #2 s2
        convert_idx<<<148, 256, 0, s2>>>(ei);                 // #3 s2
        scan_phase1<<<NBLK, SCAN_B, 0, s2>>>();               // #4 s2

        alpha_kernel<<<alpha_blocks, 256>>>(w_ij, cutoff);    // #5 main <- ncu

        scan_phase2<<<1, 64, 0, s2>>>();                      // #6 s2
        scan_phase3<<<NBLK, SCAN_B, 0, s2>>>();               // #7 s2
        permute_idx<<<148, 256, 0, s2>>>();                   // #8 s2
        cudaStreamWaitEvent(s2, evQK, 0);
        dim3 gv(gx, 1);
        qkv_gemm<<<gv, 256, 0, s2>>>(x, 2);                   // #9 s2 (|| alpha)
        cudaEventRecord(evV, s2);                             // covers sort+v

        cudaStreamWaitEvent(0, evV, 0);
        edge_agg<<<agg_blocks, 256>>>(out);                   // #10 main
    } else {
        zero_and_detect<<<148, 256>>>(ei);
        convert_idx<<<148, 256>>>(ei);
        scan_phase1<<<NBLK, SCAN_B>>>();
        scan_phase2<<<1, 64>>>();
        scan_phase3<<<NBLK, SCAN_B>>>();
        permute_idx<<<148, 256>>>();
        transpose_w<<<48, 256>>>(Wq, Wk, Wv);
        dim3 g3(gx, 3);
        qkv_gemm<<<g3, 256>>>(x, 0);
        alpha_kernel<<<alpha_blocks, 256>>>(w_ij, cutoff);
        edge_agg<<<agg_blocks, 256>>>(out);
    }
}

// round 11
// speedup vs baseline: 1.0783x; 1.0783x over previous
#include <cuda_runtime.h>

#define NN 50000
#define NE 600000
#define HID 128
#define TILE_N 64
#define KCH 32
#define SCAN_B 1024
#define NBLK ((NN + SCAN_B - 1) / SCAN_B)   // 49 scan blocks

typedef unsigned long long u64;

// Scratch (static device globals — no runtime allocation).
__device__ __align__(256) float g_q[(size_t)NN * HID];
__device__ __align__(256) float g_k[(size_t)NN * HID];
__device__ __align__(256) float g_v[(size_t)NN * HID];
__device__ __align__(256) float g_WT[3 * HID * HID];
__device__ __align__(256) int   g_src[NE];
__device__ __align__(256) int   g_dst[NE];
__device__ __align__(256) int   g_count[NN];
__device__ __align__(256) int   g_start[NN + 1];
__device__ __align__(256) int   g_cursor[NN];
__device__ __align__(256) int2  g_es[NE];        // (edge id, src) sorted by dst
__device__ __align__(256) int   g_bsum[NBLK];
__device__ __align__(256) int   g_boff[NBLK];
__device__ int g_is_i32;

// ---------------------------------------------------------------------------
// f32x2 packed-FMA helpers (FFMA2 — PTX-only, exact fp32).
// ---------------------------------------------------------------------------
__device__ __forceinline__ u64 pack2(float lo, float hi) {
    u64 r; asm("mov.b64 %0, {%1, %2};" : "=l"(r) : "f"(lo), "f"(hi)); return r;
}
__device__ __forceinline__ void fma2(u64& acc, u64 a, u64 b) {
    asm("fma.rn.f32x2 %0, %1, %2, %0;" : "+l"(acc) : "l"(a), "l"(b));
}

// ---------------------------------------------------------------------------
// Kernel Z: zero counters + dtype flag + detection in one pass.
// ---------------------------------------------------------------------------
__global__ void zero_and_detect(const unsigned int* __restrict__ ei_words) {
    int t = blockIdx.x * blockDim.x + threadIdx.x;
    if (t == 0) g_is_i32 = 0;
    for (int i = t; i < NN; i += blockDim.x * gridDim.x) g_count[i] = 0;
    unsigned int acc = 0;
    for (int i = t; i < NE; i += blockDim.x * gridDim.x)
        acc |= ei_words[2 * i + 1];
    if (acc) atomicOr(&g_is_i32, 1);
}

// ---------------------------------------------------------------------------
// Kernel B: decode edge_index into g_src/g_dst AND histogram dst degrees.
// ---------------------------------------------------------------------------
__global__ void convert_idx(const unsigned int* __restrict__ ei_words) {
    int t = blockIdx.x * blockDim.x + threadIdx.x;
    int i32 = g_is_i32;
    for (int e = t; e < NE; e += blockDim.x * gridDim.x) {
        int s, d;
        if (i32) {
            s = (int)ei_words[e];
            d = (int)ei_words[NE + e];
        } else {
            s = (int)ei_words[2 * (size_t)e];
            d = (int)ei_words[2 * ((size_t)NE + e)];
        }
        g_src[e] = s;
        g_dst[e] = d;
        atomicAdd(&g_count[d], 1);
    }
}

// ---------------------------------------------------------------------------
// 3-phase parallel scan.
// ---------------------------------------------------------------------------
__global__ __launch_bounds__(SCAN_B) void scan_phase1() {
    __shared__ int ps[SCAN_B];
    int tid = threadIdx.x;
    int idx = blockIdx.x * SCAN_B + tid;
    int val = (idx < NN) ? g_count[idx] : 0;
    ps[tid] = val;
    __syncthreads();
#pragma unroll
    for (int d = 1; d < SCAN_B; d <<= 1) {
        int v = (tid >= d) ? ps[tid - d] : 0;
        __syncthreads();
        ps[tid] += v;
        __syncthreads();
    }
    if (idx < NN) g_start[idx] = ps[tid] - val;
    if (tid == SCAN_B - 1) g_bsum[blockIdx.x] = ps[tid];
}

__global__ void scan_phase2() {
    int l = threadIdx.x;             // 64 threads, NBLK=49 <= 64
    int v = (l < NBLK) ? g_bsum[l] : 0;
    int orig = v;
    __shared__ int s[64];
    s[l] = v;
    __syncthreads();
#pragma unroll
    for (int d = 1; d < 64; d <<= 1) {
        int t = (l >= d) ? s[l - d] : 0;
        __syncthreads();
        s[l] += t;
        __syncthreads();
    }
    if (l < NBLK) g_boff[l] = s[l] - orig;
    if (l == 63) g_start[NN] = s[63];
}

__global__ __launch_bounds__(SCAN_B) void scan_phase3() {
    int idx = blockIdx.x * SCAN_B + threadIdx.x;
    if (idx < NN) {
        int v = g_start[idx] + g_boff[blockIdx.x];
        g_start[idx] = v;
        g_cursor[idx] = v;
    }
}

// ---------------------------------------------------------------------------
// Kernel D: permute (edge id, src) pairs into dst-sorted order.
// ---------------------------------------------------------------------------
__global__ void permute_idx() {
    int t = blockIdx.x * blockDim.x + threadIdx.x;
    for (int e = t; e < NE; e += blockDim.x * gridDim.x) {
        int d = g_dst[e];
        int pos = atomicAdd(&g_cursor[d], 1);
        g_es[pos] = make_int2(e, g_src[e]);
    }
}

// ---------------------------------------------------------------------------
// Kernel 0: transpose the three 128x128 weight matrices (tiny).
// ---------------------------------------------------------------------------
__global__ void transpose_w(const float* __restrict__ Wq,
                            const float* __restrict__ Wk,
                            const float* __restrict__ Wv) {
    int t = blockIdx.x * blockDim.x + threadIdx.x;
    int total = 3 * HID * HID;
    for (int idx = t; idx < total; idx += blockDim.x * gridDim.x) {
        int m = idx / (HID * HID);
        int r = idx - m * (HID * HID);
        int o = r >> 7;
        int d = r & 127;
        const float* W = (m == 0) ? Wq : (m == 1) ? Wk : Wv;
        g_WT[m * HID * HID + d * HID + o] = W[o * HID + d];
    }
}

// ---------------------------------------------------------------------------
// Kernel 1: QKV GEMM (FFMA2), 3 CTAs/SM.
// ---------------------------------------------------------------------------
__global__ __launch_bounds__(256, 3) void qkv_gemm(const float* __restrict__ x,
                                                   int m_base) {
    __shared__ float wt[KCH][HID];
    __shared__ float xs[TILE_N][KCH];

    int m = blockIdx.y + m_base;
    const float* wtg = &g_WT[m * HID * HID];
    float* out = (m == 0) ? g_q : (m == 1) ? g_k : g_v;

    int node0 = blockIdx.x * TILE_N;
    int tid = threadIdx.x;
    int w = tid >> 5;
    int l = tid & 31;

    const float4* xg4 = (const float4*)x;
    int xn0 = tid >> 3,         xc0 = tid & 7;
    int xn1 = (tid + 256) >> 3, xc1 = (tid + 256) & 7;
    int gn0 = node0 + xn0, gn1 = node0 + xn1;

    u64 cxy[8], czw[8];
#pragma unroll
    for (int n = 0; n < 8; n++) { cxy[n] = 0ull; czw[n] = 0ull; }

#pragma unroll
    for (int kk = 0; kk < HID / KCH; kk++) {
        int k0 = kk * KCH;
        if (kk) __syncthreads();
        {
            float4* wt4 = (float4*)&wt[0][0];
            const float4* srcw = (const float4*)&wtg[(size_t)k0 * HID];
#pragma unroll
            for (int i = 0; i < 4; i++)
                wt4[tid + i * 256] = srcw[tid + i * 256];
        }
        {
            float4* xs4 = (float4*)&xs[0][0];
            xs4[tid] = (gn0 < NN) ? xg4[(size_t)gn0 * 32 + (k0 >> 2) + xc0]
                                  : make_float4(0.f, 0.f, 0.f, 0.f);
            xs4[tid + 256] = (gn1 < NN) ? xg4[(size_t)gn1 * 32 + (k0 >> 2) + xc1]
                                        : make_float4(0.f, 0.f, 0.f, 0.f);
        }
        __syncthreads();

#pragma unroll
        for (int d4 = 0; d4 < KCH / 4; d4++) {
            int d = d4 * 4;
            ulonglong2 w0 = *(ulonglong2*)&wt[d + 0][4 * l];
            ulonglong2 w1 = *(ulonglong2*)&wt[d + 1][4 * l];
            ulonglong2 w2 = *(ulonglong2*)&wt[d + 2][4 * l];
            ulonglong2 w3 = *(ulonglong2*)&wt[d + 3][4 * l];
#pragma unroll
            for (int n = 0; n < 8; n++) {
                float4 xv = *(float4*)&xs[8 * w + n][d];
                u64 xb0 = pack2(xv.x, xv.x);
                u64 xb1 = pack2(xv.y, xv.y);
                u64 xb2 = pack2(xv.z, xv.z);
                u64 xb3 = pack2(xv.w, xv.w);
                fma2(cxy[n], xb0, w0.x); fma2(czw[n], xb0, w0.y);
                fma2(cxy[n], xb1, w1.x); fma2(czw[n], xb1, w1.y);
                fma2(cxy[n], xb2, w2.x); fma2(czw[n], xb2, w2.y);
                fma2(cxy[n], xb3, w3.x); fma2(czw[n], xb3, w3.y);
            }
        }
    }

#pragma unroll
    for (int n = 0; n < 8; n++) {
        int gn = node0 + 8 * w + n;
        if (gn < NN) {
            ulonglong2 o2;
            o2.x = cxy[n];
            o2.y = czw[n];
            *(ulonglong2*)&out[(size_t)gn * HID + 4 * l] = o2;
        }
    }
}

// ---------------------------------------------------------------------------
// Kernel 2: FUSED dst-sorted edge kernel. One warp per dst node.
// q loaded ONCE per node (was: per edge). Per edge: k,v gathers (L2-resident:
// k+v = 51MB in 126MB L2), w_ij 512B coalesced row (DRAM stream), cutoff
// scalar. Unroll 4 -> 12 LDG.128 + 4 scalar loads in flight. Alpha computed
// in-register via quad shfl-reduce; no intermediate alpha array, no atomics.
// ---------------------------------------------------------------------------
__global__ __launch_bounds__(256) void edge_fused(
    const float* __restrict__ w_ij,
    const float* __restrict__ cutoff,
    float* __restrict__ out) {

    int node = (blockIdx.x * blockDim.x + threadIdx.x) >> 5;
    int l = threadIdx.x & 31;
    if (node >= NN) return;

    int p     = g_start[node];
    int e_end = g_start[node + 1];

    float4 q = *(const float4*)&g_q[(size_t)node * HID + 4 * l];
    float4 acc = make_float4(0.f, 0.f, 0.f, 0.f);

    for (; p + 4 <= e_end; p += 4) {
        int2 es0 = g_es[p];
        int2 es1 = g_es[p + 1];
        int2 es2 = g_es[p + 2];
        int2 es3 = g_es[p + 3];

        // Issue all 12 vector loads + 4 scalars before any math (deep MLP).
        float4 k0 = *(const float4*)&g_k[(size_t)es0.y * HID + 4 * l];
        float4 k1 = *(const float4*)&g_k[(size_t)es1.y * HID + 4 * l];
        float4 k2 = *(const float4*)&g_k[(size_t)es2.y * HID + 4 * l];
        float4 k3 = *(const float4*)&g_k[(size_t)es3.y * HID + 4 * l];
        float4 v0 = *(const float4*)&g_v[(size_t)es0.y * HID + 4 * l];
        float4 v1 = *(const float4*)&g_v[(size_t)es1.y * HID + 4 * l];
        float4 v2 = *(const float4*)&g_v[(size_t)es2.y * HID + 4 * l];
        float4 v3 = *(const float4*)&g_v[(size_t)es3.y * HID + 4 * l];
        float4 w0 = __ldcs((const float4*)&w_ij[(size_t)es0.x * HID + 4 * l]);
        float4 w1 = __ldcs((const float4*)&w_ij[(size_t)es1.x * HID + 4 * l]);
        float4 w2 = __ldcs((const float4*)&w_ij[(size_t)es2.x * HID + 4 * l]);
        float4 w3 = __ldcs((const float4*)&w_ij[(size_t)es3.x * HID + 4 * l]);
        float  c0 = __ldg(&cutoff[es0.x]);
        float  c1 = __ldg(&cutoff[es1.x]);
        float  c2 = __ldg(&cutoff[es2.x]);
        float  c3 = __ldg(&cutoff[es3.x]);

        float p0 = q.x * w0.x * k0.x + q.y * w0.y * k0.y + q.z * w0.z * k0.z + q.w * w0.w * k0.w;
        float p1 = q.x * w1.x * k1.x + q.y * w1.y * k1.y + q.z * w1.z * k1.z + q.w * w1.w * k1.w;
        float p2 = q.x * w2.x * k2.x + q.y * w2.y * k2.y + q.z * w2.z * k2.z + q.w * w2.w * k2.w;
        float p3 = q.x * w3.x * k3.x + q.y * w3.y * k3.y + q.z * w3.z * k3.z + q.w * w3.w * k3.w;

        p0 += __shfl_xor_sync(0xffffffffu, p0, 1);
        p0 += __shfl_xor_sync(0xffffffffu, p0, 2);
        p1 += __shfl_xor_sync(0xffffffffu, p1, 1);
        p1 += __shfl_xor_sync(0xffffffffu, p1, 2);
        p2 += __shfl_xor_sync(0xffffffffu, p2, 1);
        p2 += __shfl_xor_sync(0xffffffffu, p2, 2);
        p3 += __shfl_xor_sync(0xffffffffu, p3, 1);
        p3 += __shfl_xor_sync(0xffffffffu, p3, 2);

        float a0 = p0 * 0.25f * c0;
        float a1 = p1 * 0.25f * c1;
        float a2 = p2 * 0.25f * c2;
        float a3 = p3 * 0.25f * c3;

        acc.x = fmaf(a0, v0.x, fmaf(a1, v1.x, fmaf(a2, v2.x, fmaf(a3, v3.x, acc.x))));
        acc.y = fmaf(a0, v0.y, fmaf(a1, v1.y, fmaf(a2, v2.y, fmaf(a3, v3.y, acc.y))));
        acc.z = fmaf(a0, v0.z, fmaf(a1, v1.z, fmaf(a2, v2.z, fmaf(a3, v3.z, acc.z))));
        acc.w = fmaf(a0, v0.w, fmaf(a1, v1.w, fmaf(a2, v2.w, fmaf(a3, v3.w, acc.w))));
    }
    for (; p < e_end; p++) {
        int2 es0 = g_es[p];
        float4 k0 = *(const float4*)&g_k[(size_t)es0.y * HID + 4 * l];
        float4 v0 = *(const float4*)&g_v[(size_t)es0.y * HID + 4 * l];
        float4 w0 = __ldcs((const float4*)&w_ij[(size_t)es0.x * HID + 4 * l]);
        float p0 = q.x * w0.x * k0.x + q.y * w0.y * k0.y + q.z * w0.z * k0.z + q.w * w0.w * k0.w;
        p0 += __shfl_xor_sync(0xffffffffu, p0, 1);
        p0 += __shfl_xor_sync(0xffffffffu, p0, 2);
        float a0 = p0 * 0.25f * __ldg(&cutoff[es0.x]);
        acc.x = fmaf(a0, v0.x, acc.x);
        acc.y = fmaf(a0, v0.y, acc.y);
        acc.z = fmaf(a0, v0.z, acc.z);
        acc.w = fmaf(a0, v0.w, acc.w);
    }

    __stcs((float4*)&out[(size_t)node * HID + 4 * l], acc);
}

// ---------------------------------------------------------------------------
extern "C" void kernel_launch(void* const* d_in, const int* in_sizes, int n_in,
                              void* d_out, int out_size) {
    const float* x      = (const float*)d_in[0];
    const float* w_ij   = (const float*)d_in[1];
    const unsigned int* ei = (const unsigned int*)d_in[2];
    const float* cutoff = (const float*)d_in[3];
    const float* Wq     = (const float*)d_in[4];
    const float* Wk     = (const float*)d_in[5];
    const float* Wv     = (const float*)d_in[6];
    float* out = (float*)d_out;

    static cudaStream_t s2 = nullptr;
    static cudaEvent_t evFork = nullptr, evSort = nullptr;
    static bool use_streams = false;
    if (!s2 && !evFork) {
        bool ok = (cudaStreamCreateWithFlags(&s2, cudaStreamNonBlocking) == cudaSuccess)
               && (cudaEventCreateWithFlags(&evFork, cudaEventDisableTiming) == cudaSuccess)
               && (cudaEventCreateWithFlags(&evSort, cudaEventDisableTiming) == cudaSuccess);
        use_streams = ok;
    }

    int gx = (NN + TILE_N - 1) / TILE_N;
    int fused_blocks = (NN * 32 + 255) / 256;   // warp per node

    if (use_streams) {
        cudaEventRecord(evFork, 0);
        cudaStreamWaitEvent(s2, evFork, 0);

        // s2: sort chain (hidden under the GEMM chain on main)
        zero_and_detect<<<148, 256, 0, s2>>>(ei);
        convert_idx<<<148, 256, 0, s2>>>(ei);
        scan_phase1<<<NBLK, SCAN_B, 0, s2>>>();
        scan_phase2<<<1, 64, 0, s2>>>();
        scan_phase3<<<NBLK, SCAN_B, 0, s2>>>();
        permute_idx<<<148, 256, 0, s2>>>();
        cudaEventRecord(evSort, s2);

        // main: transpose -> full QKV GEMM (fused edge kernel needs q,k,v)
        transpose_w<<<48, 256>>>(Wq, Wk, Wv);
        dim3 g3(gx, 3);
        qkv_gemm<<<g3, 256>>>(x, 0);

        // join: fused edge needs sort + qkv
        cudaStreamWaitEvent(0, evSort, 0);
        edge_fused<<<fused_blocks, 256>>>(w_ij, cutoff, out);
    } else {
        zero_and_detect<<<148, 256>>>(ei);
        convert_idx<<<148, 256>>>(ei);
        scan_phase1<<<NBLK, SCAN_B>>>();
        scan_phase2<<<1, 64>>>();
        scan_phase3<<<NBLK, SCAN_B>>>();
        permute_idx<<<148, 256>>>();
        transpose_w<<<48, 256>>>(Wq, Wk, Wv);
        dim3 g3(gx, 3);
        qkv_gemm<<<g3, 256>>>(x, 0);
        edge_fused<<<fused_blocks, 256>>>(w_ij, cutoff, out);
    }
}